// round 17
// baseline (speedup 1.0000x reference)
#include <cuda_runtime.h>
#include <cstddef>

// x: (8, 16, 3, 256, 256) fp32; out: (128, 2, 256, 256) fp32
// out[bl, ch, hw] = plane(bl*3) - plane((bl-1)*3), zero when bl%16==0; ch0==ch1.
//
// Optimum memory config (coalesced float4, __ldg + __stcs streaming stores)
// in a PERSISTENT grid-stride launch: 296 blocks (2/SM x 148 SMs) x 512
// threads, ~14 iterations each. Single wave, no wave-transition/tail cost.

static constexpr int HW4 = 16384;          // 256*256/4
static constexpr int BL  = 128;            // 8*16
static constexpr int TOTAL4 = BL * HW4;    // 2,097,152 float4 elements
static constexpr int NBLOCKS = 296;        // 2 CTAs per SM on 148 SMs
static constexpr int NTHREADS = 512;
static constexpr int STRIDE = NBLOCKS * NTHREADS;   // 151,552

__global__ __launch_bounds__(NTHREADS) void dummyflow_diff_kernel(
    const float4* __restrict__ x, float4* __restrict__ out)
{
    for (int idx = blockIdx.x * NTHREADS + threadIdx.x;
         idx < TOTAL4; idx += STRIDE)
    {
        int bl = idx >> 14;         // idx / HW4
        int hw = idx & (HW4 - 1);   // idx % HW4
        int l  = bl & 15;           // warp-uniform

        float4 v;
        if (l == 0) {
            v = make_float4(0.f, 0.f, 0.f, 0.f);
        } else {
            size_t cur  = (size_t)(bl * 3)       * HW4 + hw;
            size_t prev = (size_t)((bl - 1) * 3) * HW4 + hw;
            float4 a = __ldg(&x[cur]);
            float4 p = __ldg(&x[prev]);
            v = make_float4(a.x - p.x, a.y - p.y, a.z - p.z, a.w - p.w);
        }

        size_t o = (size_t)(bl * 2) * HW4 + hw;
        __stcs(&out[o], v);         // channel 0 — streaming (evict-first)
        __stcs(&out[o + HW4], v);   // channel 1
    }
}

extern "C" void kernel_launch(void* const* d_in, const int* in_sizes, int n_in,
                              void* d_out, int out_size)
{
    const float4* x = (const float4*)d_in[0];
    float4* out = (float4*)d_out;

    dummyflow_diff_kernel<<<NBLOCKS, NTHREADS>>>(x, out);
}